// round 1
// baseline (speedup 1.0000x reference)
#include <cuda_runtime.h>
#include <cstddef>

// RoutingByAgreement: x[B, 64, 64] f32 -> v[B, 64] f32, 3 routing iterations.
// One CTA per batch row. 256 threads.
//
// Layout A: thread t -> (n = t>>2, q = t&3), holds x[n][16q .. 16q+16) in regs (xa).
// Layout B: thread t -> (g = t>>6, d = t&63), holds x[16g+j][d], j=0..15 in regs (xB).
// Layout A is loaded straight from global (fully sector-covered across the i-loop),
// spilled once into padded smem (row stride 68 floats), from which layout B is read
// with conflict-free column LDS. After that, x never touches smem again.

#ifndef EPSF
#define EPSF 1e-8f
#endif

__global__ void __launch_bounds__(256)
routing_by_agreement_kernel(const float* __restrict__ x,
                            float* __restrict__ out,
                            int B)
{
    constexpr int ROWF = 68;               // padded smem row stride (floats)
    __shared__ float sx[64 * ROWF];        // 17408 B
    __shared__ float spart[4 * 64];        // per-group partial s
    __shared__ float sv[64];               // v vector
    __shared__ float sc[64];               // softmax coefficients
    __shared__ float slog[64];             // routing logits b_n

    const int t = threadIdx.x;
    const int b = blockIdx.x;
    if (b >= B) return;

    const int n = t >> 2, q = t & 3;       // layout A coords
    const int g = t >> 6, d = t & 63;      // layout B coords

    const float* __restrict__ xb = x + (size_t)b * 4096;

    // ---- Load layout A registers + fill padded smem (one HBM read of the tile) ----
    float4 xa[4];
#pragma unroll
    for (int i = 0; i < 4; i++) {
        xa[i] = reinterpret_cast<const float4*>(xb)[t * 4 + i];
        *reinterpret_cast<float4*>(&sx[n * ROWF + q * 16 + 4 * i]) = xa[i];
    }
    if (t < 64) slog[t] = 0.0f;
    __syncthreads();

    // ---- Layout B registers: column slice, conflict-free LDS (banks = (4n+d)%32) ----
    float xB[16];
#pragma unroll
    for (int j = 0; j < 16; j++)
        xB[j] = sx[(g * 16 + j) * ROWF + d];

    float vo0 = 0.0f, vo1 = 0.0f;          // final v held by warp 0

#pragma unroll
    for (int it = 0; it < 3; it++) {
        // ---- s-phase: partial_{g}[d] = sum_{n in group g} c[n] * x[n][d] ----
        float p = 0.0f;
        if (it == 0) {
            // c = softmax(0) = 1/64 exactly
#pragma unroll
            for (int j = 0; j < 16; j++) p += xB[j];
            p *= (1.0f / 64.0f);
        } else {
#pragma unroll
            for (int j = 0; j < 16; j++) p += sc[g * 16 + j] * xB[j];
        }
        spart[g * 64 + d] = p;
        __syncthreads();

        // ---- warp 0: reduce partials, squash, produce v ----
        if (t < 32) {
            float s0 = spart[t]      + spart[64 + t]      + spart[128 + t]      + spart[192 + t];
            float s1 = spart[t + 32] + spart[64 + t + 32] + spart[128 + t + 32] + spart[192 + t + 32];
            float nsq = s0 * s0 + s1 * s1;
#pragma unroll
            for (int off = 16; off > 0; off >>= 1)
                nsq += __shfl_xor_sync(0xffffffffu, nsq, off);
            float nrm   = sqrtf(nsq);
            float scale = nsq / (1.0f + nsq) / (nrm + EPSF);
            float v0 = s0 * scale, v1 = s1 * scale;
            sv[t] = v0; sv[t + 32] = v1;
            if (it == 2) { vo0 = v0; vo1 = v1; }
        }
        if (it == 2) break;                 // uniform across CTA
        __syncthreads();                    // sv visible

        // ---- agreement phase (layout A): a_n = <x[n], v> ----
        float4 va[4];
#pragma unroll
        for (int k = 0; k < 4; k++)
            va[k] = *reinterpret_cast<float4*>(&sv[q * 16 + 4 * k]);
        float a = 0.0f;
#pragma unroll
        for (int k = 0; k < 4; k++) {
            a += xa[k].x * va[k].x + xa[k].y * va[k].y
               + xa[k].z * va[k].z + xa[k].w * va[k].w;
        }
        a += __shfl_xor_sync(0xffffffffu, a, 1);
        a += __shfl_xor_sync(0xffffffffu, a, 2);
        if (q == 0) slog[n] += a;
        __syncthreads();                    // logits visible

        // ---- softmax over 64 logits (warp 0) ----
        if (t < 32) {
            float l0 = slog[t], l1 = slog[t + 32];
            float m = fmaxf(l0, l1);
#pragma unroll
            for (int off = 16; off > 0; off >>= 1)
                m = fmaxf(m, __shfl_xor_sync(0xffffffffu, m, off));
            float e0 = __expf(l0 - m);
            float e1 = __expf(l1 - m);
            float ssum = e0 + e1;
#pragma unroll
            for (int off = 16; off > 0; off >>= 1)
                ssum += __shfl_xor_sync(0xffffffffu, ssum, off);
            float inv = 1.0f / ssum;
            sc[t] = e0 * inv; sc[t + 32] = e1 * inv;
        }
        __syncthreads();                    // sc visible for next s-phase
    }

    // ---- output ----
    if (t < 32) {
        out[(size_t)b * 64 + t]      = vo0;
        out[(size_t)b * 64 + t + 32] = vo1;
    }
}

extern "C" void kernel_launch(void* const* d_in, const int* in_sizes, int n_in,
                              void* d_out, int out_size)
{
    const float* x = (const float*)d_in[0];
    float* out = (float*)d_out;
    const int B = in_sizes[0] / 4096;      // [B, 64, 64]
    routing_by_agreement_kernel<<<B, 256>>>(x, out, B);
}

// round 3
// speedup vs baseline: 1.3869x; 1.3869x over previous
#include <cuda_runtime.h>
#include <cstddef>
#include <cstdint>

// RoutingByAgreement: x[B,64,64] f32 -> v[B,64] f32, 3 iterations.
// Persistent CTAs, double-buffered cp.async prefetch, layout-B-only compute.
// Thread t: g = t>>6 (row group), d = t&63 (column). Holds xB[j] = x[16g+j][d].

#define FULLMASK 0xffffffffu

__device__ __forceinline__ void cp_async16(void* smem_dst, const void* gsrc) {
    uint32_t s = (uint32_t)__cvta_generic_to_shared(smem_dst);
    asm volatile("cp.async.cg.shared.global [%0], [%1], 16;\n" :: "r"(s), "l"(gsrc));
}
__device__ __forceinline__ void cp_async_commit() {
    asm volatile("cp.async.commit_group;\n" ::: "memory");
}
template<int N> __device__ __forceinline__ void cp_async_wait() {
    asm volatile("cp.async.wait_group %0;\n" :: "n"(N) : "memory");
}

__global__ void __launch_bounds__(256, 5)
routing_kernel(const float* __restrict__ x, float* __restrict__ out, int B)
{
    __shared__ __align__(16) float buf[2][4096];  // 32 KB double buffer [64][64]
    __shared__ __align__(16) float spart[4 * 64]; // per-group partial s
    __shared__ __align__(16) float sAg[8 * 16];   // per-warp agreement partials
    __shared__ __align__(16) float se[64];        // exp(logits), unnormalized
    __shared__ __align__(16) float snq[8];        // per-warp |s|^2 halves

    const int t = threadIdx.x;
    const int w = t >> 5;
    const int l = t & 31;
    const int g = t >> 6;
    const int d = t & 63;
    const int stride = gridDim.x;

    // prologue: prefetch first batch into buf[0]
    const int b0 = blockIdx.x;
    {
        const float* src = x + (size_t)b0 * 4096 + t * 16;
        float* dst = &buf[0][t * 16];
#pragma unroll
        for (int i = 0; i < 4; i++) cp_async16(dst + 4 * i, src + 4 * i);
    }
    cp_async_commit();

    int k = 0;
    for (int b = b0; b < B; b += stride, k ^= 1) {
        // issue prefetch for next batch into the other buffer (fully consumed
        // and barriered during the previous loop iteration)
        const int bn = b + stride;
        if (bn < B) {
            const float* src = x + (size_t)bn * 4096 + t * 16;
            float* dst = &buf[k ^ 1][t * 16];
#pragma unroll
            for (int i = 0; i < 4; i++) cp_async16(dst + 4 * i, src + 4 * i);
        }
        cp_async_commit();
        cp_async_wait<1>();            // current batch's group retired
        __syncthreads();

        // column slice into registers (stride-64 column reads: conflict-free)
        float xB[16];
        const float* bp = &buf[k][0];
#pragma unroll
        for (int j = 0; j < 16; j++) xB[j] = bp[(g * 16 + j) * 64 + d];
        __syncthreads();               // buf[k] free for the next prefetch

        float blog = 0.0f;             // logit accumulator (owners: t < 64)
        float v = 0.0f;

#pragma unroll
        for (int it = 0; it < 3; it++) {
            // ---- s-phase: p = sum_j e_j * xB_j  (unnormalized weights) ----
            float p, zinv;
            if (it == 0) {
                p = 0.0f;
#pragma unroll
                for (int j = 0; j < 16; j++) p += xB[j];
                zinv = 1.0f / 64.0f;   // softmax(0) = 1/64
            } else {
                float zl = se[l] + se[l + 32];   // Z redundantly per warp
#pragma unroll
                for (int off = 16; off > 0; off >>= 1)
                    zl += __shfl_xor_sync(FULLMASK, zl, off);
                zinv = 1.0f / zl;
                p = 0.0f;
                const float4* e4 = reinterpret_cast<const float4*>(&se[g * 16]);
#pragma unroll
                for (int m = 0; m < 4; m++) {
                    float4 e = e4[m];  // broadcast LDS.128 (16B-aligned)
                    p += e.x * xB[4 * m] + e.y * xB[4 * m + 1]
                       + e.z * xB[4 * m + 2] + e.w * xB[4 * m + 3];
                }
            }
            spart[g * 64 + d] = p;
            __syncthreads();

            // ---- squash: every thread computes s[d], v[d] for its own d ----
            float s = (spart[d] + spart[64 + d] + spart[128 + d] + spart[192 + d]) * zinv;
            float nq = s * s;
#pragma unroll
            for (int off = 16; off > 0; off >>= 1)
                nq += __shfl_xor_sync(FULLMASK, nq, off);
            if (l == 0) snq[w] = nq;
            __syncthreads();
            float nsq = nq + snq[w ^ 1];        // add the other d-half
            float nrm = sqrtf(nsq);
            float scale = nsq / ((1.0f + nsq) * (nrm + 1e-8f));
            v = s * scale;
            if (it == 2) break;                  // uniform

            // ---- agreement: a[16g+j] = sum_d xB[j]*v, butterfly reduce-scatter ----
            float red[8];
            {
                bool hi = l & 1;
#pragma unroll
                for (int i = 0; i < 8; i++) {
                    float a0 = xB[i] * v, a1 = xB[i + 8] * v;
                    float send = hi ? a0 : a1;
                    float recv = __shfl_xor_sync(FULLMASK, send, 1);
                    red[i] = (hi ? a1 : a0) + recv;
                }
            }
#pragma unroll
            for (int kk = 1; kk < 4; kk++) {
                const int half = 8 >> kk;
                bool hi = (l >> kk) & 1;
#pragma unroll
                for (int i = 0; i < half; i++) {
                    float send = hi ? red[i] : red[i + half];
                    float recv = __shfl_xor_sync(FULLMASK, send, 1 << kk);
                    red[i] = (hi ? red[i + half] : red[i]) + recv;
                }
            }
            float ag = red[0] + __shfl_xor_sync(FULLMASK, red[0], 16);
            if (l < 16) {
                // lane l holds row index j = bitrev4(l)
                int j = ((l & 1) << 3) | ((l & 2) << 1) | ((l & 4) >> 1) | ((l & 8) >> 3);
                sAg[w * 16 + j] = ag;
            }
            __syncthreads();

            // ---- owners (t<64) accumulate logits, store unnormalized exp ----
            if (t < 64) {
                blog += sAg[(t >> 4) * 32 + (t & 15)]
                      + sAg[(t >> 4) * 32 + 16 + (t & 15)];
                se[t] = __expf(blog);   // |blog| small: shift-free softmax safe
            }
            __syncthreads();
        }

        if (t < 64) out[(size_t)b * 64 + t] = v;   // g==0 threads cover all d
    }
}

extern "C" void kernel_launch(void* const* d_in, const int* in_sizes, int n_in,
                              void* d_out, int out_size)
{
    const float* x = (const float*)d_in[0];
    float* out = (float*)d_out;
    const int B = in_sizes[0] / 4096;
    int grid = 148 * 5;                // persistent: 5 CTAs per SM
    if (grid > B) grid = B;
    routing_kernel<<<grid, 256>>>(x, out, B);
}

// round 5
// speedup vs baseline: 1.4540x; 1.0484x over previous
#include <cuda_runtime.h>
#include <cstddef>
#include <cstdint>

// RoutingByAgreement: x[B,64,64] f32 -> v[B,64] f32, 3 iterations.
// Persistent CTAs, double-buffered cp.async, layout-B compute, approx FP.
// Thread t: g = t>>6 (row group), d = t&63. Holds xB[j] = x[16g+j][d].
// Agreement: intra-warp butterfly produces per-warp HALF dot products
// (each warp holds only 32 of 64 d's); partner warps (w^1) exchange halves
// through sAg, logits stay in lane registers.

#define FULLMASK 0xffffffffu

static __device__ __forceinline__ void cp_async16(void* smem_dst, const void* gsrc) {
    uint32_t s = (uint32_t)__cvta_generic_to_shared(smem_dst);
    asm volatile("cp.async.cg.shared.global [%0], [%1], 16;\n" :: "r"(s), "l"(gsrc));
}
static __device__ __forceinline__ void cp_async_commit() {
    asm volatile("cp.async.commit_group;\n" ::: "memory");
}
template<int N> static __device__ __forceinline__ void cp_async_wait() {
    asm volatile("cp.async.wait_group %0;\n" :: "n"(N) : "memory");
}
static __device__ __forceinline__ float frcp(float x) {
    float r; asm("rcp.approx.f32 %0, %1;" : "=f"(r) : "f"(x)); return r;
}
static __device__ __forceinline__ float frsq(float x) {
    float r; asm("rsqrt.approx.f32 %0, %1;" : "=f"(r) : "f"(x)); return r;
}

__global__ void __launch_bounds__(256, 5)
routing_kernel(const float* __restrict__ x, float* __restrict__ out, int B)
{
    __shared__ __align__(16) float buf[2][4096];  // 32 KB double buffer [64][64]
    __shared__ __align__(16) float spart[4 * 64]; // per-group partial s
    __shared__ __align__(16) float sAg[8 * 16];   // per-warp half-agreements
    __shared__ __align__(16) float se[64];        // exp(logits), unnormalized

    const int t = threadIdx.x;
    const int w = t >> 5;
    const int l = t & 31;
    const int g = t >> 6;
    const int d = t & 63;
    const int stride = gridDim.x;
    // lane's agreement row within its group: j = bitrev4(l & 15)
    const int jrow = ((l & 1) << 3) | ((l & 2) << 1) | ((l & 4) >> 1) | ((l & 8) >> 3);
    const int seIdx = g * 16 + jrow;

    // prologue: prefetch first batch into buf[0]
    const int b0 = blockIdx.x;
    {
        const float* src = x + (size_t)b0 * 4096 + t * 16;
        float* dst = &buf[0][t * 16];
#pragma unroll
        for (int i = 0; i < 4; i++) cp_async16(dst + 4 * i, src + 4 * i);
    }
    cp_async_commit();

    int k = 0;
    for (int b = b0; b < B; b += stride, k ^= 1) {
        const int bn = b + stride;
        if (bn < B) {
            const float* src = x + (size_t)bn * 4096 + t * 16;
            float* dst = &buf[k ^ 1][t * 16];
#pragma unroll
            for (int i = 0; i < 4; i++) cp_async16(dst + 4 * i, src + 4 * i);
        }
        cp_async_commit();
        cp_async_wait<1>();            // current batch's group retired
        __syncthreads();

        // column slice into registers (bank = d mod 32 = lane: conflict-free)
        float xB[16];
        const float* bp = &buf[k][0];
#pragma unroll
        for (int j = 0; j < 16; j++) xB[j] = bp[(g * 16 + j) * 64 + d];
        __syncthreads();               // buf[k] free for the next prefetch

        float blog = 0.0f;             // per-lane logit for row (g, jrow)
        float v = 0.0f;

#pragma unroll
        for (int it = 0; it < 3; it++) {
            // ---- s-phase: p = sum_j e_j * xB_j (unnormalized weights) ----
            float p, zinv;
            if (it == 0) {
                p = 0.0f;
#pragma unroll
                for (int j = 0; j < 16; j++) p += xB[j];
                zinv = 1.0f / 64.0f;   // softmax(0) = 1/64
            } else {
                float zl = se[l] + se[l + 32];
#pragma unroll
                for (int off = 16; off > 0; off >>= 1)
                    zl += __shfl_xor_sync(FULLMASK, zl, off);
                zinv = frcp(zl);
                p = 0.0f;
                const float4* e4 = reinterpret_cast<const float4*>(&se[g * 16]);
#pragma unroll
                for (int m = 0; m < 4; m++) {
                    float4 e = e4[m];  // broadcast LDS.128
                    p += e.x * xB[4 * m] + e.y * xB[4 * m + 1]
                       + e.z * xB[4 * m + 2] + e.w * xB[4 * m + 3];
                }
            }
            spart[g * 64 + d] = p;
            __syncthreads();           // barrier A

            // ---- squash: both d-halves in-thread (pairs {d, d^32} over the
            //      warp cover all 64 columns exactly once) ----
            const int dx = d ^ 32;
            float s0 = (spart[d]  + spart[64 + d]  + spart[128 + d]  + spart[192 + d])  * zinv;
            float s1 = (spart[dx] + spart[64 + dx] + spart[128 + dx] + spart[192 + dx]) * zinv;
            float nq = s0 * s0 + s1 * s1;
#pragma unroll
            for (int off = 16; off > 0; off >>= 1)
                nq += __shfl_xor_sync(FULLMASK, nq, off);
            float rn    = frsq(nq + 1e-20f);
            float nrm   = nq * rn;                         // sqrt(nq)
            float scale = nq * frcp((1.0f + nq) * (nrm + 1e-8f));
            v = s0 * scale;            // v for this thread's own d
            if (it == 2) break;        // uniform exit

            // ---- agreement: butterfly reduce-scatter of xB[j]*v over this
            //      warp's 32 d's -> per-warp HALF dot product ----
            float red[8];
            {
                bool hi = l & 1;
#pragma unroll
                for (int i = 0; i < 8; i++) {
                    float a0 = xB[i] * v, a1 = xB[i + 8] * v;
                    float send = hi ? a0 : a1;
                    float recv = __shfl_xor_sync(FULLMASK, send, 1);
                    red[i] = (hi ? a1 : a0) + recv;
                }
            }
#pragma unroll
            for (int kk = 1; kk < 4; kk++) {
                const int half = 8 >> kk;
                bool hi = (l >> kk) & 1;
#pragma unroll
                for (int i = 0; i < half; i++) {
                    float send = hi ? red[i] : red[i + half];
                    float recv = __shfl_xor_sync(FULLMASK, send, 1 << kk);
                    red[i] = (hi ? red[i + half] : red[i]) + recv;
                }
            }
            float agHalf = red[0] + __shfl_xor_sync(FULLMASK, red[0], 16);
            if (l < 16) sAg[w * 16 + jrow] = agHalf;   // publish my warp's half
            __syncthreads();           // barrier B

            // full agreement = my half + partner warp's (w^1) half
            blog += agHalf + sAg[(w ^ 1) * 16 + jrow];
            if (l < 16) se[seIdx] = __expf(blog);
            __syncthreads();           // barrier C (also protects spart WAR)
        }

        if (t < 64) out[(size_t)b * 64 + t] = v;   // g==0 covers all d
    }
}

extern "C" void kernel_launch(void* const* d_in, const int* in_sizes, int n_in,
                              void* d_out, int out_size)
{
    const float* x = (const float*)d_in[0];
    float* out = (float*)d_out;
    const int B = in_sizes[0] / 4096;
    int grid = 148 * 5;                // persistent: 5 CTAs per SM
    if (grid > B) grid = B;
    routing_kernel<<<grid, 256>>>(x, out, B);
}